// round 12
// baseline (speedup 1.0000x reference)
#include <cuda_runtime.h>

#define B_ 4
#define C_ 64
#define N_ 8192
#define K_ 32
#define R2_ 0.04f
#define BN_EPS_ 1e-5f
#define NC 5
#define NCELL (NC * NC * NC)
#define INFB 0x7f800000u

typedef unsigned long long ull;

#define FMA2ACC(acc, a, bb) asm("fma.rn.f32x2 %0, %1, %2, %0;" : "+l"(acc) : "l"(a), "l"(bb))

__device__ __forceinline__ ull pack2(float lo, float hi) {
    ull r; asm("mov.b64 %0, {%1, %2};" : "=l"(r) : "f"(lo), "f"(hi)); return r;
}
__device__ __forceinline__ void unpack2(ull v, float& lo, float& hi) {
    asm("mov.b64 {%0, %1}, %2;" : "=f"(lo), "=f"(hi) : "l"(v));
}
__device__ __forceinline__ int cell_clamp(float v) {
    int c = (int)(v * 5.0f);
    return min(NC - 1, max(0, c));
}

// Scratch (static __device__ arrays — no allocation)
__device__ float  g_F[B_ * N_ * C_];      // F[b][n][d] = fea row . W_fea[d] * scale
__device__ int    g_gidx[B_ * N_ * K_];   // final (masked) neighbor indices
__device__ ull    g_WsT2[32 * 64];        // packed (w[2c],w[2c+1]) per d, BN-scaled
__device__ float  g_Wc[3 * 64];           // coord weights * scale
__device__ float  g_bias[64];             // BN-folded bias
// grid structures
__device__ int    g_cnt[B_ * NCELL];      // zeroed by agg (last kernel) for replay
__device__ int    g_cellStart[B_ * (NCELL + 1)];
__device__ int    g_rank[B_ * N_];        // intra-cell rank per point
__device__ float4 g_pts[B_ * N_];         // cell-sorted (x,y,z,sq)
__device__ int    g_pid[B_ * N_];         // original point index

// ---------------------------------------------------------------------------
// K1: W-fold block [0] + grid count blocks [1,129). Count records each
// point's intra-cell rank (atomic return) so scatter needs no atomics.
// Intra-cell order is nondeterministic but the KNN selection key
// (d_bits, idx) is visit-order invariant => output deterministic.
// ---------------------------------------------------------------------------
__global__ __launch_bounds__(256) void k_prep(
    const float* __restrict__ coor,
    const float* __restrict__ W,
    const float* __restrict__ gamma_, const float* __restrict__ beta_,
    const float* __restrict__ rmean, const float* __restrict__ rvar)
{
    const int bid = blockIdx.x;
    const int tid = threadIdx.x;
    if (bid == 0) {
        if (tid < 64) {
            float sc = gamma_[tid] * rsqrtf(rvar[tid] + BN_EPS_);
            g_bias[tid] = beta_[tid] - rmean[tid] * sc;
            g_Wc[tid]       = W[tid * 67 + 64] * sc;
            g_Wc[64 + tid]  = W[tid * 67 + 65] * sc;
            g_Wc[128 + tid] = W[tid * 67 + 66] * sc;
        }
        for (int e = tid; e < 32 * 64; e += 256) {
            int c2 = e >> 6, d = e & 63;
            float sc = gamma_[d] * rsqrtf(rvar[d] + BN_EPS_);
            g_WsT2[e] = pack2(W[d * 67 + 2 * c2] * sc, W[d * 67 + 2 * c2 + 1] * sc);
        }
    } else {
        int id = (bid - 1) * 256 + tid;
        int b = id / N_, n = id % N_;
        const float* cb = coor + b * 3 * N_;
        int cx = cell_clamp(cb[n]);
        int cy = cell_clamp(cb[N_ + n]);
        int cz = cell_clamp(cb[2 * N_ + n]);
        g_rank[id] = atomicAdd(&g_cnt[b * NCELL + (cz * NC + cy) * NC + cx], 1);
    }
}

// ---------------------------------------------------------------------------
// K2 (fused): blocks [0,128) = scatter (with LOCAL prefix scan of the 125
// cell counts), blocks [128,1152) = F GEMM.
// ---------------------------------------------------------------------------
__global__ __launch_bounds__(256) void scatter_fgemm(
    const float* __restrict__ coor, const float* __restrict__ fea)
{
    __shared__ ull s_wt[32 * 64];                       // fgemm: [c2][d]  16 KB
    __shared__ __align__(16) float sfea[32 * 66];       // fgemm: [n][c] padded
    __shared__ int sPre[NCELL + 1];                     // scatter: local scan
    const int bid = blockIdx.x;
    const int tid = threadIdx.x;

    if (bid < 128) {
        // ---- scatter: 32 blocks per batch, b uniform per block ----
        const int b  = bid >> 5;
        const int id = bid * 256 + tid;
        const int n  = id % N_;
        if (tid < 32) {
            int carry = 0;
            if (tid == 0) sPre[0] = 0;
            for (int c0 = 0; c0 < NCELL; c0 += 32) {
                int i = c0 + tid;
                int v = (i < NCELL) ? g_cnt[b * NCELL + i] : 0;
#pragma unroll
                for (int o = 1; o < 32; o <<= 1) {
                    int tv = __shfl_up_sync(0xffffffffu, v, o);
                    if (tid >= o) v += tv;
                }
                if (i < NCELL) sPre[i + 1] = carry + v;
                carry += __shfl_sync(0xffffffffu, v, 31);
            }
        }
        __syncthreads();
        for (int i = tid; i <= NCELL; i += 256)
            g_cellStart[b * (NCELL + 1) + i] = sPre[i];

        const float* cb = coor + b * 3 * N_;
        float x = cb[n], y = cb[N_ + n], z = cb[2 * N_ + n];
        float sq = fmaf(x, x, fmaf(y, y, z * z));   // same chain as query side
        int cx = cell_clamp(x), cy = cell_clamp(y), cz = cell_clamp(z);
        int pos = sPre[(cz * NC + cy) * NC + cx] + g_rank[id];
        g_pts[b * N_ + pos] = make_float4(x, y, z, sq);
        g_pid[b * N_ + pos] = n;
    } else {
        // ---- F GEMM: warp = 8 d's x 32 n's, 8 outputs/thread ----
        const int fb  = bid - 128;          // [0,1024)
        const int b   = fb >> 8;            // 256 n-chunks per batch
        const int n0  = (fb & 255) * 32;
        const int w   = tid >> 5, lane = tid & 31;

        for (int e = tid; e < 32 * 64; e += 256) s_wt[e] = g_WsT2[e];
#pragma unroll
        for (int i = 0; i < 8; i++) {
            int c = w * 8 + i;
            sfea[lane * 66 + c] = fea[(b * 64 + c) * N_ + n0 + lane];
        }
        __syncthreads();

        const ull* frow = reinterpret_cast<const ull*>(sfea + lane * 66);
        const int d0 = w * 8;
        ull acc[8];
#pragma unroll
        for (int j = 0; j < 8; j++) acc[j] = 0ull;
#pragma unroll 8
        for (int c2 = 0; c2 < 32; c2++) {
            ull f = frow[c2];
            const ull* wr = s_wt + c2 * 64 + d0;
            ulonglong2 w01 = *reinterpret_cast<const ulonglong2*>(wr);
            ulonglong2 w23 = *reinterpret_cast<const ulonglong2*>(wr + 2);
            ulonglong2 w45 = *reinterpret_cast<const ulonglong2*>(wr + 4);
            ulonglong2 w67 = *reinterpret_cast<const ulonglong2*>(wr + 6);
            FMA2ACC(acc[0], f, w01.x); FMA2ACC(acc[1], f, w01.y);
            FMA2ACC(acc[2], f, w23.x); FMA2ACC(acc[3], f, w23.y);
            FMA2ACC(acc[4], f, w45.x); FMA2ACC(acc[5], f, w45.y);
            FMA2ACC(acc[6], f, w67.x); FMA2ACC(acc[7], f, w67.y);
        }
        float o[8];
#pragma unroll
        for (int j = 0; j < 8; j++) {
            float lo, hi; unpack2(acc[j], lo, hi);
            o[j] = lo + hi;
        }
        float4* dst = reinterpret_cast<float4*>(
            g_F + ((size_t)(b * N_ + n0 + lane)) * 64 + d0);
        dst[0] = make_float4(o[0], o[1], o[2], o[3]);
        dst[1] = make_float4(o[4], o[5], o[6], o[7]);
    }
}

// ---------------------------------------------------------------------------
// KNN: one warp per query, distributed top-32 heap keyed on (d_bits, idx)
// (visit-order invariant), nearest-SLAB-first with provable early exit.
// NEW: the 27 neighbor cells collapse into 9 x-slabs (x cells are adjacent in
// g_cellStart), each one contiguous range of ~25 points — ~3x fewer batch
// iterations. Slab box min-dist (min over its cells) is a valid lower bound
// for every contained point, so pruning/early-exit remain conservative; any
// extra points from individually-prunable cells simply fail d <= R^2.
// ---------------------------------------------------------------------------
__global__ __launch_bounds__(256) void knn_kernel(const float* __restrict__ coor) {
    __shared__ ull s_stage[8][32];

    const int b    = blockIdx.y;
    const int warp = threadIdx.x >> 5;
    const int lane = threadIdx.x & 31;
    const int q    = blockIdx.x * 8 + warp;

    const float* cb = coor + b * 3 * N_;
    const float qx  = cb[q];
    const float qy  = cb[N_ + q];
    const float qz  = cb[2 * N_ + q];
    const float qsq = fmaf(qx, qx, fmaf(qy, qy, qz * qz));

    // per-lane slab range + slab box min-dist (9 slabs on lanes 0..8)
    int s = 0, e = 0;
    unsigned mdu = INFB;
    {
        int qcx = cell_clamp(qx), qcy = cell_clamp(qy), qcz = cell_clamp(qz);
        if (lane < 9) {
            int cy = qcy + (lane % 3) - 1;
            int cz = qcz + (lane / 3) - 1;
            if (cy >= 0 && cy < NC && cz >= 0 && cz < NC) {
                int x0 = max(qcx - 1, 0), x1 = min(qcx + 1, NC - 1);
                float bx0 = x0 * 0.2f, bx1 = (x1 + 1) * 0.2f;
                float by0 = cy * 0.2f, bz0 = cz * 0.2f;
                float ddx = fmaxf(0.f, fmaxf(bx0 - qx, qx - bx1));
                float ddy = fmaxf(0.f, fmaxf(by0 - qy, qy - (by0 + 0.2f)));
                float ddz = fmaxf(0.f, fmaxf(bz0 - qz, qz - (bz0 + 0.2f)));
                float md = ddx * ddx + ddy * ddy + ddz * ddz;
                if (md <= R2_ + 1e-5f) {
                    int base = b * (NCELL + 1) + (cz * NC + cy) * NC;
                    s = g_cellStart[base + x0];
                    e = g_cellStart[base + x1 + 1];
                    mdu = __float_as_uint(md);
                }
            }
        }
    }

    unsigned mydb  = INFB;
    unsigned myidx = 0u;
    unsigned cmd = INFB, cmi = 0u;
    int maxlane = 0;
    int count = 0;                 // warp-uniform filled slot count

    const float4* pts = g_pts + b * N_;
    const int*    pid = g_pid + b * N_;

#pragma unroll 1
    for (int r = 0; r < 9; r++) {
        unsigned rmin = __reduce_min_sync(0xffffffffu, mdu);
        if (rmin == INFB) break;
        if (count == 32 &&
            __uint_as_float(cmd) + 4e-6f < __uint_as_float(rmin)) break;
        int j = __ffs(__ballot_sync(0xffffffffu, mdu == rmin)) - 1;
        int cs = __shfl_sync(0xffffffffu, s, j);
        int ce = __shfl_sync(0xffffffffu, e, j);
        if (lane == j) mdu = INFB;

        for (int i0 = cs; i0 < ce; i0 += 32) {
            int i = i0 + lane;
            bool act = i < ce;
            float4 p = act ? pts[i]
                           : make_float4(0.f, 0.f, 0.f, __int_as_float(0x7f800000));
            float dot = fmaf(qx, p.x, fmaf(qy, p.y, qz * p.z));
            float d   = fmaf(-2.f, dot, qsq + p.w);
            d = fmaxf(d, 0.f);
            unsigned db = __float_as_uint(d);
            unsigned pv = act ? (unsigned)pid[i] : 0u;
            bool ok = act && (d <= R2_) &&
                      (db < cmd || (db == cmd && pv < cmi));
            unsigned mask = __ballot_sync(0xffffffffu, ok);

            // ---- batched fill (heap not yet full) ----
            if (count < 32 && mask) {
                int m    = __popc(mask);
                int take = min(32 - count, m);
                int rank = __popc(mask & ((1u << lane) - 1u));
                if (ok && rank < take)
                    s_stage[warp][rank] = ((ull)db << 32) | pv;
                __syncwarp();
                int rr = lane - count;
                if (rr >= 0 && rr < take) {
                    ull v = s_stage[warp][rr];
                    mydb  = (unsigned)(v >> 32);
                    myidx = (unsigned)v;
                }
                count += take;
                if (take == m) mask = 0;
                else
                    for (int t = 0; t < take; t++) mask &= mask - 1;
                if (count == 32) {
                    cmd = __reduce_max_sync(0xffffffffu, mydb);
                    bool eq = (mydb == cmd);
                    cmi = __reduce_max_sync(0xffffffffu, eq ? myidx : 0u);
                    maxlane = __ffs(__ballot_sync(0xffffffffu,
                                        eq && (myidx == cmi))) - 1;
                }
            }

            // ---- eviction (heap full), unchanged ----
            while (mask) {
                int jj = __ffs(mask) - 1;
                mask &= mask - 1;
                unsigned djb = __shfl_sync(0xffffffffu, db, jj);
                unsigned cj  = __shfl_sync(0xffffffffu, pv, jj);
                if (djb < cmd || (djb == cmd && cj < cmi)) {
                    if (lane == maxlane) { mydb = djb; myidx = cj; }
                    cmd = __reduce_max_sync(0xffffffffu, mydb);
                    bool eq = (mydb == cmd);
                    cmi = __reduce_max_sync(0xffffffffu, eq ? myidx : 0u);
                    maxlane = __ffs(__ballot_sync(0xffffffffu,
                                        eq && (myidx == cmi))) - 1;
                }
            }
        }
    }
    int finalIdx = (__uint_as_float(mydb) <= R2_) ? (int)myidx : q;
    g_gidx[(b * N_ + q) * K_ + lane] = finalIdx;
}

// ---------------------------------------------------------------------------
// Aggregation in CELL-SORTED query order: block = 4 consecutive positions in
// g_pid — same-cell queries whose neighbor sets overlap heavily, so the F
// gathers hit L1/L2. Per-query math bit-identical (g_pts holds the exact
// coord bits); only the output store is scattered (cheap vs gather savings).
// Block (0,0) also re-zeroes g_cnt for the next graph replay.
// ---------------------------------------------------------------------------
__global__ __launch_bounds__(128) void agg_kernel(const float* __restrict__ coor,
                                                  float* __restrict__ out) {
    __shared__ __align__(16) float4 scc[4 * 32];

    const int b    = blockIdx.y;
    const int p0   = blockIdx.x * 4;     // position in cell-sorted order
    const int tid  = threadIdx.x;
    const int q    = tid >> 5;           // warp = query (by position)
    const int lane = tid & 31;
    const float* cb = coor + b * 3 * N_;

    if (blockIdx.x == 0 && b == 0)
        for (int i = tid; i < B_ * NCELL; i += 128) g_cnt[i] = 0;

    const int qid = g_pid[b * N_ + p0 + q];
    {
        float4 qp = g_pts[b * N_ + p0 + q];   // exact coord bits of query
        int id = g_gidx[(b * N_ + qid) * K_ + lane];
        scc[tid] = make_float4((cb[id] - qp.x) * 5.0f,
                               (cb[N_ + id] - qp.y) * 5.0f,
                               (cb[2 * N_ + id] - qp.z) * 5.0f,
                               __int_as_float(id));
    }
    __syncthreads();

    const ull wx2 = reinterpret_cast<const ull*>(g_Wc)[lane];
    const ull wy2 = reinterpret_cast<const ull*>(g_Wc + 64)[lane];
    const ull wz2 = reinterpret_cast<const ull*>(g_Wc + 128)[lane];
    const float2 bb = reinterpret_cast<const float2*>(g_bias)[lane];
    const float* Fb = g_F + (size_t)(b * N_) * 64;

    float m0 = __int_as_float(0xff800000), m1 = m0;
#pragma unroll 4
    for (int k = 0; k < 32; k++) {
        float4 cc = scc[q * 32 + k];
        int id = __float_as_int(cc.w);
        ull y = reinterpret_cast<const ull*>(Fb + id * 64)[lane];
        FMA2ACC(y, pack2(cc.x, cc.x), wx2);
        FMA2ACC(y, pack2(cc.y, cc.y), wy2);
        FMA2ACC(y, pack2(cc.z, cc.z), wz2);
        float y0, y1; unpack2(y, y0, y1);
        m0 = fmaxf(m0, y0);
        m1 = fmaxf(m1, y1);
    }
    out[(b * 64 + 2 * lane) * N_ + qid]     = fmaxf(m0 + bb.x, 0.f);
    out[(b * 64 + 2 * lane + 1) * N_ + qid] = fmaxf(m1 + bb.y, 0.f);
}

// ---------------------------------------------------------------------------
extern "C" void kernel_launch(void* const* d_in, const int* in_sizes, int n_in,
                              void* d_out, int out_size) {
    const float* coor  = (const float*)d_in[0];
    const float* fea   = (const float*)d_in[1];
    const float* W     = (const float*)d_in[2];
    const float* gamma = (const float*)d_in[3];
    const float* beta  = (const float*)d_in[4];
    const float* rmean = (const float*)d_in[5];
    const float* rvar  = (const float*)d_in[6];
    float* out = (float*)d_out;

    k_prep<<<1 + B_ * N_ / 256, 256>>>(coor, W, gamma, beta, rmean, rvar);
    scatter_fgemm<<<128 + (N_ / 32) * B_, 256>>>(coor, fea);
    knn_kernel<<<dim3(N_ / 8, B_), 256>>>(coor);
    agg_kernel<<<dim3(N_ / 4, B_), 128>>>(coor, out);
}

// round 13
// speedup vs baseline: 1.0954x; 1.0954x over previous
#include <cuda_runtime.h>

#define B_ 4
#define C_ 64
#define N_ 8192
#define K_ 32
#define R2_ 0.04f
#define BN_EPS_ 1e-5f
#define NC 5
#define NCELL (NC * NC * NC)
#define INFB 0x7f800000u

typedef unsigned long long ull;

#define FMA2ACC(acc, a, bb) asm("fma.rn.f32x2 %0, %1, %2, %0;" : "+l"(acc) : "l"(a), "l"(bb))

__device__ __forceinline__ ull pack2(float lo, float hi) {
    ull r; asm("mov.b64 %0, {%1, %2};" : "=l"(r) : "f"(lo), "f"(hi)); return r;
}
__device__ __forceinline__ void unpack2(ull v, float& lo, float& hi) {
    asm("mov.b64 {%0, %1}, %2;" : "=f"(lo), "=f"(hi) : "l"(v));
}
__device__ __forceinline__ int cell_clamp(float v) {
    int c = (int)(v * 5.0f);
    return min(NC - 1, max(0, c));
}

// Scratch (static __device__ arrays — no allocation)
__device__ float  g_F[B_ * N_ * C_];      // F[b][n][d] = fea row . W_fea[d] * scale
__device__ ull    g_WsT2[32 * 64];        // packed (w[2c],w[2c+1]) per d, BN-scaled
__device__ float  g_Wc[3 * 64];           // coord weights * scale
__device__ float  g_bias[64];             // BN-folded bias
// grid structures
__device__ int    g_cnt[B_ * NCELL];      // zeroed by knn_agg for next replay
__device__ int    g_cellStart[B_ * (NCELL + 1)];
__device__ int    g_rank[B_ * N_];        // intra-cell rank per point
__device__ float4 g_pts[B_ * N_];         // cell-sorted (x,y,z,sq)
__device__ int    g_pid[B_ * N_];         // original point index

// ---------------------------------------------------------------------------
// K1: W-fold block [0] + grid count blocks [1,129). Count records each
// point's intra-cell rank (atomic return) so scatter needs no atomics.
// Intra-cell order is nondeterministic but the KNN selection key
// (d_bits, idx) is visit-order invariant => output deterministic.
// ---------------------------------------------------------------------------
__global__ __launch_bounds__(256) void k_prep(
    const float* __restrict__ coor,
    const float* __restrict__ W,
    const float* __restrict__ gamma_, const float* __restrict__ beta_,
    const float* __restrict__ rmean, const float* __restrict__ rvar)
{
    const int bid = blockIdx.x;
    const int tid = threadIdx.x;
    if (bid == 0) {
        if (tid < 64) {
            float sc = gamma_[tid] * rsqrtf(rvar[tid] + BN_EPS_);
            g_bias[tid] = beta_[tid] - rmean[tid] * sc;
            g_Wc[tid]       = W[tid * 67 + 64] * sc;
            g_Wc[64 + tid]  = W[tid * 67 + 65] * sc;
            g_Wc[128 + tid] = W[tid * 67 + 66] * sc;
        }
        for (int e = tid; e < 32 * 64; e += 256) {
            int c2 = e >> 6, d = e & 63;
            float sc = gamma_[d] * rsqrtf(rvar[d] + BN_EPS_);
            g_WsT2[e] = pack2(W[d * 67 + 2 * c2] * sc, W[d * 67 + 2 * c2 + 1] * sc);
        }
    } else {
        int id = (bid - 1) * 256 + tid;
        int b = id / N_, n = id % N_;
        const float* cb = coor + b * 3 * N_;
        int cx = cell_clamp(cb[n]);
        int cy = cell_clamp(cb[N_ + n]);
        int cz = cell_clamp(cb[2 * N_ + n]);
        g_rank[id] = atomicAdd(&g_cnt[b * NCELL + (cz * NC + cy) * NC + cx], 1);
    }
}

// ---------------------------------------------------------------------------
// K2 (fused): blocks [0,128) = scatter (with LOCAL prefix scan of the 125
// cell counts), blocks [128,1152) = F GEMM.
// ---------------------------------------------------------------------------
__global__ __launch_bounds__(256) void scatter_fgemm(
    const float* __restrict__ coor, const float* __restrict__ fea)
{
    __shared__ ull s_wt[32 * 64];                       // fgemm: [c2][d]  16 KB
    __shared__ __align__(16) float sfea[32 * 66];       // fgemm: [n][c] padded
    __shared__ int sPre[NCELL + 1];                     // scatter: local scan
    const int bid = blockIdx.x;
    const int tid = threadIdx.x;

    if (bid < 128) {
        // ---- scatter: 32 blocks per batch, b uniform per block ----
        const int b  = bid >> 5;
        const int id = bid * 256 + tid;
        const int n  = id % N_;
        if (tid < 32) {
            int carry = 0;
            if (tid == 0) sPre[0] = 0;
            for (int c0 = 0; c0 < NCELL; c0 += 32) {
                int i = c0 + tid;
                int v = (i < NCELL) ? g_cnt[b * NCELL + i] : 0;
#pragma unroll
                for (int o = 1; o < 32; o <<= 1) {
                    int tv = __shfl_up_sync(0xffffffffu, v, o);
                    if (tid >= o) v += tv;
                }
                if (i < NCELL) sPre[i + 1] = carry + v;
                carry += __shfl_sync(0xffffffffu, v, 31);
            }
        }
        __syncthreads();
        for (int i = tid; i <= NCELL; i += 256)
            g_cellStart[b * (NCELL + 1) + i] = sPre[i];

        const float* cb = coor + b * 3 * N_;
        float x = cb[n], y = cb[N_ + n], z = cb[2 * N_ + n];
        float sq = fmaf(x, x, fmaf(y, y, z * z));   // same chain as query side
        int cx = cell_clamp(x), cy = cell_clamp(y), cz = cell_clamp(z);
        int pos = sPre[(cz * NC + cy) * NC + cx] + g_rank[id];
        g_pts[b * N_ + pos] = make_float4(x, y, z, sq);
        g_pid[b * N_ + pos] = n;
    } else {
        // ---- F GEMM: warp = 8 d's x 32 n's, 8 outputs/thread ----
        const int fb  = bid - 128;          // [0,1024)
        const int b   = fb >> 8;            // 256 n-chunks per batch
        const int n0  = (fb & 255) * 32;
        const int w   = tid >> 5, lane = tid & 31;

        for (int e = tid; e < 32 * 64; e += 256) s_wt[e] = g_WsT2[e];
#pragma unroll
        for (int i = 0; i < 8; i++) {
            int c = w * 8 + i;
            sfea[lane * 66 + c] = fea[(b * 64 + c) * N_ + n0 + lane];
        }
        __syncthreads();

        const ull* frow = reinterpret_cast<const ull*>(sfea + lane * 66);
        const int d0 = w * 8;
        ull acc[8];
#pragma unroll
        for (int j = 0; j < 8; j++) acc[j] = 0ull;
#pragma unroll 8
        for (int c2 = 0; c2 < 32; c2++) {
            ull f = frow[c2];
            const ull* wr = s_wt + c2 * 64 + d0;
            ulonglong2 w01 = *reinterpret_cast<const ulonglong2*>(wr);
            ulonglong2 w23 = *reinterpret_cast<const ulonglong2*>(wr + 2);
            ulonglong2 w45 = *reinterpret_cast<const ulonglong2*>(wr + 4);
            ulonglong2 w67 = *reinterpret_cast<const ulonglong2*>(wr + 6);
            FMA2ACC(acc[0], f, w01.x); FMA2ACC(acc[1], f, w01.y);
            FMA2ACC(acc[2], f, w23.x); FMA2ACC(acc[3], f, w23.y);
            FMA2ACC(acc[4], f, w45.x); FMA2ACC(acc[5], f, w45.y);
            FMA2ACC(acc[6], f, w67.x); FMA2ACC(acc[7], f, w67.y);
        }
        float o[8];
#pragma unroll
        for (int j = 0; j < 8; j++) {
            float lo, hi; unpack2(acc[j], lo, hi);
            o[j] = lo + hi;
        }
        float4* dst = reinterpret_cast<float4*>(
            g_F + ((size_t)(b * N_ + n0 + lane)) * 64 + d0);
        dst[0] = make_float4(o[0], o[1], o[2], o[3]);
        dst[1] = make_float4(o[4], o[5], o[6], o[7]);
    }
}

// ---------------------------------------------------------------------------
// K3 (fused KNN + aggregation): block = 8 warps = 8 consecutive queries.
// Phase 1 = R11's knn verbatim: per-cell box prune (27 cells), nearest-cell-
// first, order-invariant (d_bits, idx) heap, batched fill, provable early
// exit. Phase 2 = agg in-place: lane k of the warp already holds neighbor
// slot k, so g_gidx never exists; F-gathers (L2-bound) now overlap other
// warps' knn compute (issue-bound). Math byte-identical to R11's agg.
// Block (0,0) re-zeroes g_cnt for the next graph replay.
// ---------------------------------------------------------------------------
__global__ __launch_bounds__(256) void knn_agg(const float* __restrict__ coor,
                                               float* __restrict__ out) {
    __shared__ ull s_stage[8][32];
    __shared__ __align__(16) float4 scc[8][32];
    __shared__ float sout[8 * 64];

    const int b    = blockIdx.y;
    const int warp = threadIdx.x >> 5;
    const int lane = threadIdx.x & 31;
    const int q0   = blockIdx.x * 8;
    const int q    = q0 + warp;
    const int tid  = threadIdx.x;

    if (blockIdx.x == 0 && b == 0)
        for (int i = tid; i < B_ * NCELL; i += 256) g_cnt[i] = 0;

    const float* cb = coor + b * 3 * N_;
    const float qx  = cb[q];
    const float qy  = cb[N_ + q];
    const float qz  = cb[2 * N_ + q];
    const float qsq = fmaf(qx, qx, fmaf(qy, qy, qz * qz));

    // per-lane cell range + box min-dist (27 neighborhood cells, lanes 0..26)
    int s = 0, e = 0;
    unsigned mdu = INFB;
    {
        int qcx = cell_clamp(qx), qcy = cell_clamp(qy), qcz = cell_clamp(qz);
        if (lane < 27) {
            int cx = qcx + (lane % 3) - 1;
            int cy = qcy + ((lane / 3) % 3) - 1;
            int cz = qcz + (lane / 9) - 1;
            if (cx >= 0 && cx < NC && cy >= 0 && cy < NC && cz >= 0 && cz < NC) {
                float bx0 = cx * 0.2f, by0 = cy * 0.2f, bz0 = cz * 0.2f;
                float ddx = fmaxf(0.f, fmaxf(bx0 - qx, qx - (bx0 + 0.2f)));
                float ddy = fmaxf(0.f, fmaxf(by0 - qy, qy - (by0 + 0.2f)));
                float ddz = fmaxf(0.f, fmaxf(bz0 - qz, qz - (bz0 + 0.2f)));
                float md = ddx * ddx + ddy * ddy + ddz * ddz;
                if (md <= R2_ + 1e-5f) {
                    int ci = b * (NCELL + 1) + (cz * NC + cy) * NC + cx;
                    s = g_cellStart[ci];
                    e = g_cellStart[ci + 1];
                    mdu = __float_as_uint(md);
                }
            }
        }
    }

    unsigned mydb  = INFB;
    unsigned myidx = 0u;
    unsigned cmd = INFB, cmi = 0u;
    int maxlane = 0;
    int count = 0;                 // warp-uniform filled slot count

    const float4* pts = g_pts + b * N_;
    const int*    pid = g_pid + b * N_;

#pragma unroll 1
    for (int r = 0; r < 27; r++) {
        unsigned rmin = __reduce_min_sync(0xffffffffu, mdu);
        if (rmin == INFB) break;
        if (count == 32 &&
            __uint_as_float(cmd) + 4e-6f < __uint_as_float(rmin)) break;
        int j = __ffs(__ballot_sync(0xffffffffu, mdu == rmin)) - 1;
        int cs = __shfl_sync(0xffffffffu, s, j);
        int ce = __shfl_sync(0xffffffffu, e, j);
        if (lane == j) mdu = INFB;

        for (int i0 = cs; i0 < ce; i0 += 32) {
            int i = i0 + lane;
            bool act = i < ce;
            float4 p = act ? pts[i]
                           : make_float4(0.f, 0.f, 0.f, __int_as_float(0x7f800000));
            float dot = fmaf(qx, p.x, fmaf(qy, p.y, qz * p.z));
            float d   = fmaf(-2.f, dot, qsq + p.w);
            d = fmaxf(d, 0.f);
            unsigned db = __float_as_uint(d);
            unsigned pv = act ? (unsigned)pid[i] : 0u;
            bool ok = act && (d <= R2_) &&
                      (db < cmd || (db == cmd && pv < cmi));
            unsigned mask = __ballot_sync(0xffffffffu, ok);

            // ---- batched fill (heap not yet full) ----
            if (count < 32 && mask) {
                int m    = __popc(mask);
                int take = min(32 - count, m);
                int rank = __popc(mask & ((1u << lane) - 1u));
                if (ok && rank < take)
                    s_stage[warp][rank] = ((ull)db << 32) | pv;
                __syncwarp();
                int rr = lane - count;
                if (rr >= 0 && rr < take) {
                    ull v = s_stage[warp][rr];
                    mydb  = (unsigned)(v >> 32);
                    myidx = (unsigned)v;
                }
                count += take;
                if (take == m) mask = 0;
                else
                    for (int t = 0; t < take; t++) mask &= mask - 1;
                if (count == 32) {
                    cmd = __reduce_max_sync(0xffffffffu, mydb);
                    bool eq = (mydb == cmd);
                    cmi = __reduce_max_sync(0xffffffffu, eq ? myidx : 0u);
                    maxlane = __ffs(__ballot_sync(0xffffffffu,
                                        eq && (myidx == cmi))) - 1;
                }
            }

            // ---- eviction (heap full) ----
            while (mask) {
                int jj = __ffs(mask) - 1;
                mask &= mask - 1;
                unsigned djb = __shfl_sync(0xffffffffu, db, jj);
                unsigned cj  = __shfl_sync(0xffffffffu, pv, jj);
                if (djb < cmd || (djb == cmd && cj < cmi)) {
                    if (lane == maxlane) { mydb = djb; myidx = cj; }
                    cmd = __reduce_max_sync(0xffffffffu, mydb);
                    bool eq = (mydb == cmd);
                    cmi = __reduce_max_sync(0xffffffffu, eq ? myidx : 0u);
                    maxlane = __ffs(__ballot_sync(0xffffffffu,
                                        eq && (myidx == cmi))) - 1;
                }
            }
        }
    }
    const int id = (__uint_as_float(mydb) <= R2_) ? (int)myidx : q;

    // ======== phase 2: aggregation (lane k holds neighbor slot k) ========
    scc[warp][lane] = make_float4((cb[id] - qx) * 5.0f,           // /RADIUS
                                  (cb[N_ + id] - qy) * 5.0f,
                                  (cb[2 * N_ + id] - qz) * 5.0f,
                                  __int_as_float(id));
    __syncwarp();

    const ull wx2 = reinterpret_cast<const ull*>(g_Wc)[lane];
    const ull wy2 = reinterpret_cast<const ull*>(g_Wc + 64)[lane];
    const ull wz2 = reinterpret_cast<const ull*>(g_Wc + 128)[lane];
    const float2 bb = reinterpret_cast<const float2*>(g_bias)[lane];
    const float* Fb = g_F + (size_t)(b * N_) * 64;

    float m0 = __int_as_float(0xff800000), m1 = m0;   // -inf
#pragma unroll 4
    for (int k = 0; k < 32; k++) {
        float4 cc = scc[warp][k];                      // broadcast LDS.128
        int nid = __float_as_int(cc.w);
        ull y = reinterpret_cast<const ull*>(Fb + nid * 64)[lane]; // LDG.64
        FMA2ACC(y, pack2(cc.x, cc.x), wx2);
        FMA2ACC(y, pack2(cc.y, cc.y), wy2);
        FMA2ACC(y, pack2(cc.z, cc.z), wz2);
        float y0, y1; unpack2(y, y0, y1);
        m0 = fmaxf(m0, y0);
        m1 = fmaxf(m1, y1);
    }
    sout[warp * 64 + 2 * lane]     = fmaxf(m0 + bb.x, 0.f);
    sout[warp * 64 + 2 * lane + 1] = fmaxf(m1 + bb.y, 0.f);
    __syncthreads();

    // transposed store: thread t -> d-row (t>>2), query pair (t&3)*2
    {
        int d = tid >> 2, qp = (tid & 3) * 2;
        float2 v = make_float2(sout[qp * 64 + d], sout[(qp + 1) * 64 + d]);
        *reinterpret_cast<float2*>(&out[(b * 64 + d) * N_ + q0 + qp]) = v;
    }
}

// ---------------------------------------------------------------------------
extern "C" void kernel_launch(void* const* d_in, const int* in_sizes, int n_in,
                              void* d_out, int out_size) {
    const float* coor  = (const float*)d_in[0];
    const float* fea   = (const float*)d_in[1];
    const float* W     = (const float*)d_in[2];
    const float* gamma = (const float*)d_in[3];
    const float* beta  = (const float*)d_in[4];
    const float* rmean = (const float*)d_in[5];
    const float* rvar  = (const float*)d_in[6];
    float* out = (float*)d_out;

    k_prep<<<1 + B_ * N_ / 256, 256>>>(coor, W, gamma, beta, rmean, rvar);
    scatter_fgemm<<<128 + (N_ / 32) * B_, 256>>>(coor, fea);
    knn_agg<<<dim3(N_ / 8, B_), 256>>>(coor, out);
}

// round 14
// speedup vs baseline: 1.1853x; 1.0821x over previous
#include <cuda_runtime.h>

#define B_ 4
#define C_ 64
#define N_ 8192
#define K_ 32
#define R2_ 0.04f
#define BN_EPS_ 1e-5f
#define NC 5
#define NCELL (NC * NC * NC)
#define INFB 0x7f800000u

typedef unsigned long long ull;

#define FMA2ACC(acc, a, bb) asm("fma.rn.f32x2 %0, %1, %2, %0;" : "+l"(acc) : "l"(a), "l"(bb))

__device__ __forceinline__ ull pack2(float lo, float hi) {
    ull r; asm("mov.b64 %0, {%1, %2};" : "=l"(r) : "f"(lo), "f"(hi)); return r;
}
__device__ __forceinline__ void unpack2(ull v, float& lo, float& hi) {
    asm("mov.b64 {%0, %1}, %2;" : "=f"(lo), "=f"(hi) : "l"(v));
}
__device__ __forceinline__ int cell_clamp(float v) {
    int c = (int)(v * 5.0f);
    return min(NC - 1, max(0, c));
}

// Scratch (static __device__ arrays — no allocation)
__device__ float  g_F[B_ * N_ * C_];      // F[b][n][d] = fea row . W_fea[d] * scale
__device__ int    g_gidx[B_ * N_ * K_];   // final (masked) neighbor indices
__device__ ull    g_WsT2[32 * 64];        // packed (w[2c],w[2c+1]) per d, BN-scaled
__device__ float  g_Wc[3 * 64];           // coord weights * scale
__device__ float  g_bias[64];             // BN-folded bias
// grid structures
__device__ int    g_cnt[B_ * NCELL];      // zeroed by agg (last kernel) for replay
__device__ int    g_cellStart[B_ * (NCELL + 1)];
__device__ int    g_rank[B_ * N_];        // intra-cell rank per point
__device__ float4 g_pts[B_ * N_];         // cell-sorted (x,y,z,sq)
__device__ int    g_pid[B_ * N_];         // original point index

// ---------------------------------------------------------------------------
// K1: W-fold block [0] + grid count blocks [1,129). TWO-LEVEL count: local
// rank via shared-memory atomics, then ONE aggregated global atomicAdd per
// non-empty cell per block (halves the per-address LTS serialization chains
// that made the old version 7.6us). Rank uniqueness per cell preserved;
// intra-cell order nondeterministic — covered by the order-invariant
// (d_bits, idx) selection key in knn.
// ---------------------------------------------------------------------------
__global__ __launch_bounds__(256) void k_prep(
    const float* __restrict__ coor,
    const float* __restrict__ W,
    const float* __restrict__ gamma_, const float* __restrict__ beta_,
    const float* __restrict__ rmean, const float* __restrict__ rvar)
{
    const int bid = blockIdx.x;
    const int tid = threadIdx.x;
    if (bid == 0) {
        if (tid < 64) {
            float sc = gamma_[tid] * rsqrtf(rvar[tid] + BN_EPS_);
            g_bias[tid] = beta_[tid] - rmean[tid] * sc;
            g_Wc[tid]       = W[tid * 67 + 64] * sc;
            g_Wc[64 + tid]  = W[tid * 67 + 65] * sc;
            g_Wc[128 + tid] = W[tid * 67 + 66] * sc;
        }
        for (int e = tid; e < 32 * 64; e += 256) {
            int c2 = e >> 6, d = e & 63;
            float sc = gamma_[d] * rsqrtf(rvar[d] + BN_EPS_);
            g_WsT2[e] = pack2(W[d * 67 + 2 * c2] * sc, W[d * 67 + 2 * c2 + 1] * sc);
        }
    } else {
        __shared__ int scnt[NCELL];
        __shared__ int sbase[NCELL];
        for (int i = tid; i < NCELL; i += 256) scnt[i] = 0;
        __syncthreads();

        const int id = (bid - 1) * 256 + tid;
        const int b = id / N_, n = id % N_;     // b uniform per block (32/batch)
        const float* cb = coor + b * 3 * N_;
        int cx = cell_clamp(cb[n]);
        int cy = cell_clamp(cb[N_ + n]);
        int cz = cell_clamp(cb[2 * N_ + n]);
        const int ci = (cz * NC + cy) * NC + cx;
        int lr = atomicAdd(&scnt[ci], 1);
        __syncthreads();

        for (int i = tid; i < NCELL; i += 256) {
            int c = scnt[i];
            if (c) sbase[i] = atomicAdd(&g_cnt[b * NCELL + i], c);
        }
        __syncthreads();
        g_rank[id] = sbase[ci] + lr;
    }
}

// ---------------------------------------------------------------------------
// K2 (fused): blocks [0,128) = scatter (with LOCAL prefix scan of the 125
// cell counts), blocks [128,1152) = F GEMM.  (UNCHANGED from R11)
// ---------------------------------------------------------------------------
__global__ __launch_bounds__(256) void scatter_fgemm(
    const float* __restrict__ coor, const float* __restrict__ fea)
{
    __shared__ ull s_wt[32 * 64];                       // fgemm: [c2][d]  16 KB
    __shared__ __align__(16) float sfea[32 * 66];       // fgemm: [n][c] padded
    __shared__ int sPre[NCELL + 1];                     // scatter: local scan
    const int bid = blockIdx.x;
    const int tid = threadIdx.x;

    if (bid < 128) {
        // ---- scatter: 32 blocks per batch, b uniform per block ----
        const int b  = bid >> 5;
        const int id = bid * 256 + tid;
        const int n  = id % N_;
        if (tid < 32) {
            int carry = 0;
            if (tid == 0) sPre[0] = 0;
            for (int c0 = 0; c0 < NCELL; c0 += 32) {
                int i = c0 + tid;
                int v = (i < NCELL) ? g_cnt[b * NCELL + i] : 0;
#pragma unroll
                for (int o = 1; o < 32; o <<= 1) {
                    int tv = __shfl_up_sync(0xffffffffu, v, o);
                    if (tid >= o) v += tv;
                }
                if (i < NCELL) sPre[i + 1] = carry + v;
                carry += __shfl_sync(0xffffffffu, v, 31);
            }
        }
        __syncthreads();
        for (int i = tid; i <= NCELL; i += 256)
            g_cellStart[b * (NCELL + 1) + i] = sPre[i];

        const float* cb = coor + b * 3 * N_;
        float x = cb[n], y = cb[N_ + n], z = cb[2 * N_ + n];
        float sq = fmaf(x, x, fmaf(y, y, z * z));   // same chain as query side
        int cx = cell_clamp(x), cy = cell_clamp(y), cz = cell_clamp(z);
        int pos = sPre[(cz * NC + cy) * NC + cx] + g_rank[id];
        g_pts[b * N_ + pos] = make_float4(x, y, z, sq);
        g_pid[b * N_ + pos] = n;
    } else {
        // ---- F GEMM: warp = 8 d's x 32 n's, 8 outputs/thread ----
        const int fb  = bid - 128;          // [0,1024)
        const int b   = fb >> 8;            // 256 n-chunks per batch
        const int n0  = (fb & 255) * 32;
        const int w   = tid >> 5, lane = tid & 31;

        for (int e = tid; e < 32 * 64; e += 256) s_wt[e] = g_WsT2[e];
#pragma unroll
        for (int i = 0; i < 8; i++) {
            int c = w * 8 + i;
            sfea[lane * 66 + c] = fea[(b * 64 + c) * N_ + n0 + lane];
        }
        __syncthreads();

        const ull* frow = reinterpret_cast<const ull*>(sfea + lane * 66);
        const int d0 = w * 8;
        ull acc[8];
#pragma unroll
        for (int j = 0; j < 8; j++) acc[j] = 0ull;
#pragma unroll 8
        for (int c2 = 0; c2 < 32; c2++) {
            ull f = frow[c2];
            const ull* wr = s_wt + c2 * 64 + d0;
            ulonglong2 w01 = *reinterpret_cast<const ulonglong2*>(wr);
            ulonglong2 w23 = *reinterpret_cast<const ulonglong2*>(wr + 2);
            ulonglong2 w45 = *reinterpret_cast<const ulonglong2*>(wr + 4);
            ulonglong2 w67 = *reinterpret_cast<const ulonglong2*>(wr + 6);
            FMA2ACC(acc[0], f, w01.x); FMA2ACC(acc[1], f, w01.y);
            FMA2ACC(acc[2], f, w23.x); FMA2ACC(acc[3], f, w23.y);
            FMA2ACC(acc[4], f, w45.x); FMA2ACC(acc[5], f, w45.y);
            FMA2ACC(acc[6], f, w67.x); FMA2ACC(acc[7], f, w67.y);
        }
        float o[8];
#pragma unroll
        for (int j = 0; j < 8; j++) {
            float lo, hi; unpack2(acc[j], lo, hi);
            o[j] = lo + hi;
        }
        float4* dst = reinterpret_cast<float4*>(
            g_F + ((size_t)(b * N_ + n0 + lane)) * 64 + d0);
        dst[0] = make_float4(o[0], o[1], o[2], o[3]);
        dst[1] = make_float4(o[4], o[5], o[6], o[7]);
    }
}

// ---------------------------------------------------------------------------
// KNN: one warp per query, distributed top-32 heap keyed on (d_bits, idx)
// (visit-order invariant), per-cell box prune (27 cells), nearest-cell-first,
// batched heap fill, provable early exit.  (UNCHANGED from R11 — the R12
// slab merge and R13 fusion both regressed.)
// ---------------------------------------------------------------------------
__global__ __launch_bounds__(256) void knn_kernel(const float* __restrict__ coor) {
    __shared__ ull s_stage[8][32];

    const int b    = blockIdx.y;
    const int warp = threadIdx.x >> 5;
    const int lane = threadIdx.x & 31;
    const int q    = blockIdx.x * 8 + warp;

    const float* cb = coor + b * 3 * N_;
    const float qx  = cb[q];
    const float qy  = cb[N_ + q];
    const float qz  = cb[2 * N_ + q];
    const float qsq = fmaf(qx, qx, fmaf(qy, qy, qz * qz));

    int s = 0, e = 0;
    unsigned mdu = INFB;
    {
        int qcx = cell_clamp(qx), qcy = cell_clamp(qy), qcz = cell_clamp(qz);
        if (lane < 27) {
            int cx = qcx + (lane % 3) - 1;
            int cy = qcy + ((lane / 3) % 3) - 1;
            int cz = qcz + (lane / 9) - 1;
            if (cx >= 0 && cx < NC && cy >= 0 && cy < NC && cz >= 0 && cz < NC) {
                float bx0 = cx * 0.2f, by0 = cy * 0.2f, bz0 = cz * 0.2f;
                float ddx = fmaxf(0.f, fmaxf(bx0 - qx, qx - (bx0 + 0.2f)));
                float ddy = fmaxf(0.f, fmaxf(by0 - qy, qy - (by0 + 0.2f)));
                float ddz = fmaxf(0.f, fmaxf(bz0 - qz, qz - (bz0 + 0.2f)));
                float md = ddx * ddx + ddy * ddy + ddz * ddz;
                if (md <= R2_ + 1e-5f) {
                    int ci = b * (NCELL + 1) + (cz * NC + cy) * NC + cx;
                    s = g_cellStart[ci];
                    e = g_cellStart[ci + 1];
                    mdu = __float_as_uint(md);
                }
            }
        }
    }

    unsigned mydb  = INFB;
    unsigned myidx = 0u;
    unsigned cmd = INFB, cmi = 0u;
    int maxlane = 0;
    int count = 0;                 // warp-uniform filled slot count

    const float4* pts = g_pts + b * N_;
    const int*    pid = g_pid + b * N_;

#pragma unroll 1
    for (int r = 0; r < 27; r++) {
        unsigned rmin = __reduce_min_sync(0xffffffffu, mdu);
        if (rmin == INFB) break;
        if (count == 32 &&
            __uint_as_float(cmd) + 4e-6f < __uint_as_float(rmin)) break;
        int j = __ffs(__ballot_sync(0xffffffffu, mdu == rmin)) - 1;
        int cs = __shfl_sync(0xffffffffu, s, j);
        int ce = __shfl_sync(0xffffffffu, e, j);
        if (lane == j) mdu = INFB;

        for (int i0 = cs; i0 < ce; i0 += 32) {
            int i = i0 + lane;
            bool act = i < ce;
            float4 p = act ? pts[i]
                           : make_float4(0.f, 0.f, 0.f, __int_as_float(0x7f800000));
            float dot = fmaf(qx, p.x, fmaf(qy, p.y, qz * p.z));
            float d   = fmaf(-2.f, dot, qsq + p.w);
            d = fmaxf(d, 0.f);
            unsigned db = __float_as_uint(d);
            unsigned pv = act ? (unsigned)pid[i] : 0u;
            bool ok = act && (d <= R2_) &&
                      (db < cmd || (db == cmd && pv < cmi));
            unsigned mask = __ballot_sync(0xffffffffu, ok);

            // ---- batched fill (heap not yet full) ----
            if (count < 32 && mask) {
                int m    = __popc(mask);
                int take = min(32 - count, m);
                int rank = __popc(mask & ((1u << lane) - 1u));
                if (ok && rank < take)
                    s_stage[warp][rank] = ((ull)db << 32) | pv;
                __syncwarp();
                int rr = lane - count;
                if (rr >= 0 && rr < take) {
                    ull v = s_stage[warp][rr];
                    mydb  = (unsigned)(v >> 32);
                    myidx = (unsigned)v;
                }
                count += take;
                if (take == m) mask = 0;
                else
                    for (int t = 0; t < take; t++) mask &= mask - 1;
                if (count == 32) {
                    cmd = __reduce_max_sync(0xffffffffu, mydb);
                    bool eq = (mydb == cmd);
                    cmi = __reduce_max_sync(0xffffffffu, eq ? myidx : 0u);
                    maxlane = __ffs(__ballot_sync(0xffffffffu,
                                        eq && (myidx == cmi))) - 1;
                }
            }

            // ---- eviction (heap full) ----
            while (mask) {
                int jj = __ffs(mask) - 1;
                mask &= mask - 1;
                unsigned djb = __shfl_sync(0xffffffffu, db, jj);
                unsigned cj  = __shfl_sync(0xffffffffu, pv, jj);
                if (djb < cmd || (djb == cmd && cj < cmi)) {
                    if (lane == maxlane) { mydb = djb; myidx = cj; }
                    cmd = __reduce_max_sync(0xffffffffu, mydb);
                    bool eq = (mydb == cmd);
                    cmi = __reduce_max_sync(0xffffffffu, eq ? myidx : 0u);
                    maxlane = __ffs(__ballot_sync(0xffffffffu,
                                        eq && (myidx == cmi))) - 1;
                }
            }
        }
    }
    int finalIdx = (__uint_as_float(mydb) <= R2_) ? (int)myidx : q;
    g_gidx[(b * N_ + q) * K_ + lane] = finalIdx;
}

// ---------------------------------------------------------------------------
// Aggregation: warp = one query (64 d's, 2 per lane via f32x2), index order.
// Block (0,0) re-zeroes g_cnt for the next graph replay.
// Only change vs R11: k-loop unroll 4 -> 8 (MLP 8, latency-bound kernel).
// ---------------------------------------------------------------------------
__global__ __launch_bounds__(128) void agg_kernel(const float* __restrict__ coor,
                                                  float* __restrict__ out) {
    __shared__ __align__(16) float4 scc[4 * 32];
    __shared__ float sout[4 * 64];

    const int b    = blockIdx.y;
    const int q0   = blockIdx.x * 4;
    const int tid  = threadIdx.x;
    const int q    = tid >> 5;
    const int lane = tid & 31;
    const float* cb = coor + b * 3 * N_;

    if (blockIdx.x == 0 && b == 0)
        for (int i = tid; i < B_ * NCELL; i += 128) g_cnt[i] = 0;

    {
        int id = g_gidx[(b * N_ + q0 + q) * K_ + lane];
        scc[tid] = make_float4((cb[id] - cb[q0 + q]) * 5.0f,
                               (cb[N_ + id] - cb[N_ + q0 + q]) * 5.0f,
                               (cb[2 * N_ + id] - cb[2 * N_ + q0 + q]) * 5.0f,
                               __int_as_float(id));
    }
    __syncthreads();

    const ull wx2 = reinterpret_cast<const ull*>(g_Wc)[lane];
    const ull wy2 = reinterpret_cast<const ull*>(g_Wc + 64)[lane];
    const ull wz2 = reinterpret_cast<const ull*>(g_Wc + 128)[lane];
    const float2 bb = reinterpret_cast<const float2*>(g_bias)[lane];
    const float* Fb = g_F + (size_t)(b * N_) * 64;

    float m0 = __int_as_float(0xff800000), m1 = m0;
#pragma unroll 8
    for (int k = 0; k < 32; k++) {
        float4 cc = scc[q * 32 + k];
        int id = __float_as_int(cc.w);
        ull y = reinterpret_cast<const ull*>(Fb + id * 64)[lane];
        FMA2ACC(y, pack2(cc.x, cc.x), wx2);
        FMA2ACC(y, pack2(cc.y, cc.y), wy2);
        FMA2ACC(y, pack2(cc.z, cc.z), wz2);
        float y0, y1; unpack2(y, y0, y1);
        m0 = fmaxf(m0, y0);
        m1 = fmaxf(m1, y1);
    }
    sout[q * 64 + 2 * lane]     = fmaxf(m0 + bb.x, 0.f);
    sout[q * 64 + 2 * lane + 1] = fmaxf(m1 + bb.y, 0.f);
    __syncthreads();

    if (tid < 64) {
        float4 v = make_float4(sout[tid], sout[64 + tid],
                               sout[128 + tid], sout[192 + tid]);
        *reinterpret_cast<float4*>(&out[(b * 64 + tid) * N_ + q0]) = v;
    }
}

// ---------------------------------------------------------------------------
extern "C" void kernel_launch(void* const* d_in, const int* in_sizes, int n_in,
                              void* d_out, int out_size) {
    const float* coor  = (const float*)d_in[0];
    const float* fea   = (const float*)d_in[1];
    const float* W     = (const float*)d_in[2];
    const float* gamma = (const float*)d_in[3];
    const float* beta  = (const float*)d_in[4];
    const float* rmean = (const float*)d_in[5];
    const float* rvar  = (const float*)d_in[6];
    float* out = (float*)d_out;

    k_prep<<<1 + B_ * N_ / 256, 256>>>(coor, W, gamma, beta, rmean, rvar);
    scatter_fgemm<<<128 + (N_ / 32) * B_, 256>>>(coor, fea);
    knn_kernel<<<dim3(N_ / 8, B_), 256>>>(coor);
    agg_kernel<<<dim3(N_ / 4, B_), 128>>>(coor, out);
}